// round 1
// baseline (speedup 1.0000x reference)
#include <cuda_runtime.h>
#include <cstdint>

#define BB 8
#define SS 4096
#define DD 256
#define NROWS (BB*SS)
#define NEGV  (-1000000000.0f)
#define NSPLIT 8
#define SCHUNK (SS/NSPLIT)   // 512

// ---- scratch (no allocations allowed) ----
__device__ float g_inv_b[NROWS];
__device__ float g_mul[NROWS];
__device__ float g_add[NROWS];
__device__ float g_s1[BB*DD*DD];              // 2 MB
__device__ float g_s1p[NSPLIT][BB*DD*DD];     // 16 MB split partials
__device__ int   g_mask_kind;                 // 0=int32, 1=uint8/bool, 2=float32

// ---------------------------------------------------------------------------
// Kernel 0: sniff the serialized dtype of the boolean mask.
// Reads only the first 8192 32-bit words (32 KB) — safe for all 3 layouts
// (bool layout is exactly 32768 bytes). Deterministic given the input.
// ---------------------------------------------------------------------------
__global__ void k_detect(const unsigned int* __restrict__ m) {
    __shared__ int s_u8, s_f;
    if (threadIdx.x == 0) { s_u8 = 0; s_f = 0; }
    __syncthreads();
    for (int i = threadIdx.x; i < 8192; i += blockDim.x) {
        unsigned v = m[i];
        if (v == 0x3F800000u)      s_f  = 1;   // float 1.0
        else if (v > 1u)           s_u8 = 1;   // packed bytes -> bool layout
    }
    __syncthreads();
    if (threadIdx.x == 0) g_mask_kind = s_u8 ? 1 : (s_f ? 2 : 0);
}

// ---------------------------------------------------------------------------
// Kernel 1: per-row sum of squares for q and k; fold mask into (mul, add):
//   score[s, :] = q[s, :] * mul[s] + add[s]
// ---------------------------------------------------------------------------
__global__ void k_rownorm(const float* __restrict__ q,
                          const float* __restrict__ k,
                          const void*  __restrict__ mask) {
    int row  = blockIdx.x * 8 + (threadIdx.x >> 5);
    int lane = threadIdx.x & 31;
    const float4* q4 = (const float4*)(q + (size_t)row * DD);
    const float4* k4 = (const float4*)(k + (size_t)row * DD);
    float sa = 0.f, sb = 0.f;
#pragma unroll
    for (int j = 0; j < 2; j++) {
        float4 a = q4[lane + 32 * j];
        sa += a.x*a.x + a.y*a.y + a.z*a.z + a.w*a.w;
        float4 b = k4[lane + 32 * j];
        sb += b.x*b.x + b.y*b.y + b.z*b.z + b.w*b.w;
    }
#pragma unroll
    for (int o = 16; o; o >>= 1) {
        sa += __shfl_xor_sync(0xFFFFFFFFu, sa, o);
        sb += __shfl_xor_sync(0xFFFFFFFFu, sb, o);
    }
    if (lane == 0) {
        g_inv_b[row] = 1.0f / sb;
        int kind = g_mask_kind;
        bool ms;
        if (kind == 1)      ms = ((const unsigned char*)mask)[row] != 0;
        else if (kind == 2) ms = ((const float*)mask)[row] != 0.0f;
        else                ms = ((const int*)mask)[row] != 0;
        g_mul[row] = ms ? 0.0f : 1.0f / sa;
        g_add[row] = ms ? NEGV : 0.0f;
    }
}

// ---------------------------------------------------------------------------
// Kernel 2: s1 partials.  C[d,e] = sum_s (k[s,d]*inv_b[s]) * v[s,e]
// Split-K over NSPLIT chunks of 512 rows.  128x128 tile, 8x8 per thread.
// Grid: (4 tiles, NSPLIT, B), 256 threads.
// ---------------------------------------------------------------------------
__global__ void __launch_bounds__(256, 2)
k_s1(const float* __restrict__ K, const float* __restrict__ V) {
    const int b     = blockIdx.z;
    const int split = blockIdx.y;
    const int m0    = (blockIdx.x >> 1) * 128;
    const int n0    = (blockIdx.x & 1) * 128;
    const int s0    = split * SCHUNK;

    __shared__ float As[16][128];
    __shared__ float Bs[16][128];

    const int tid = threadIdx.x;
    const int tx = tid & 15, ty = tid >> 4;

    float c[8][8];
#pragma unroll
    for (int i = 0; i < 8; i++)
#pragma unroll
        for (int j = 0; j < 8; j++) c[i][j] = 0.f;

    const float* Kb   = K + (size_t)b * SS * DD;
    const float* Vb   = V + (size_t)b * SS * DD;
    const float* invb = g_inv_b + b * SS;

    for (int ks = 0; ks < SCHUNK; ks += 16) {
#pragma unroll
        for (int j = 0; j < 2; j++) {
            int idx = tid + j * 256;          // 0..511
            int r   = idx >> 5;               // 0..15
            int c4  = idx & 31;               // 0..31
            int s   = s0 + ks + r;
            float ib = invb[s];
            float4 av = *(const float4*)(Kb + (size_t)s * DD + m0 + c4 * 4);
            av.x *= ib; av.y *= ib; av.z *= ib; av.w *= ib;
            *(float4*)(&As[r][c4 * 4]) = av;
            *(float4*)(&Bs[r][c4 * 4]) =
                *(const float4*)(Vb + (size_t)s * DD + n0 + c4 * 4);
        }
        __syncthreads();
#pragma unroll
        for (int kk = 0; kk < 16; kk++) {
            float4 a0 = *(float4*)&As[kk][ty * 4];
            float4 a1 = *(float4*)&As[kk][ty * 4 + 64];
            float4 b0 = *(float4*)&Bs[kk][tx * 4];
            float4 b1 = *(float4*)&Bs[kk][tx * 4 + 64];
            float a[8] = {a0.x,a0.y,a0.z,a0.w, a1.x,a1.y,a1.z,a1.w};
            float bv[8] = {b0.x,b0.y,b0.z,b0.w, b1.x,b1.y,b1.z,b1.w};
#pragma unroll
            for (int i = 0; i < 8; i++)
#pragma unroll
                for (int j = 0; j < 8; j++) c[i][j] += a[i] * bv[j];
        }
        __syncthreads();
    }

    float* out = g_s1p[split] + (size_t)b * DD * DD;
#pragma unroll
    for (int i = 0; i < 8; i++) {
        int mr = m0 + ty * 4 + (i & 3) + ((i >> 2) << 6);
        float* orow = out + (size_t)mr * DD + n0;
        *(float4*)(orow + tx * 4)      = make_float4(c[i][0], c[i][1], c[i][2], c[i][3]);
        *(float4*)(orow + tx * 4 + 64) = make_float4(c[i][4], c[i][5], c[i][6], c[i][7]);
    }
}

// ---------------------------------------------------------------------------
// Kernel 3: reduce the split partials into g_s1.
// ---------------------------------------------------------------------------
__global__ void k_reduce() {
    int i = blockIdx.x * 256 + threadIdx.x;   // over B*D*D = 524288
    float s = 0.f;
#pragma unroll
    for (int p = 0; p < NSPLIT; p++) s += g_s1p[p][i];
    g_s1[i] = s;
}

// ---------------------------------------------------------------------------
// Kernel 4: s2 = (Q*mul + add) @ s1 / 256.  128x128 tile, K = 256.
// Grid: (2 ntiles, 32 mtiles, B), 256 threads.
// ---------------------------------------------------------------------------
__global__ void __launch_bounds__(256, 2)
k_s2(const float* __restrict__ Q, float* __restrict__ Out) {
    const int b  = blockIdx.z;
    const int m0 = blockIdx.y * 128;
    const int n0 = blockIdx.x * 128;

    __shared__ float As[16][132];   // padded: transpose stores
    __shared__ float Bs[16][128];

    const int tid = threadIdx.x;
    const int tx = tid & 15, ty = tid >> 4;

    float c[8][8];
#pragma unroll
    for (int i = 0; i < 8; i++)
#pragma unroll
        for (int j = 0; j < 8; j++) c[i][j] = 0.f;

    const float* Qb  = Q + (size_t)b * SS * DD;
    const float* mul = g_mul + b * SS;
    const float* add = g_add + b * SS;
    const float* s1b = g_s1 + (size_t)b * DD * DD;

    for (int k0 = 0; k0 < DD; k0 += 16) {
        // A: 128 rows(s) x 16 cols(d), transposed into As[d][s]
#pragma unroll
        for (int j = 0; j < 2; j++) {
            int idx = tid + j * 256;       // 0..511 float4s
            int r   = idx >> 2;            // s_local 0..127
            int d4  = idx & 3;             // 0..3
            int s   = m0 + r;
            float4 v = *(const float4*)(Qb + (size_t)s * DD + k0 + d4 * 4);
            float mm = mul[s], aa = add[s];
            As[d4 * 4 + 0][r] = v.x * mm + aa;
            As[d4 * 4 + 1][r] = v.y * mm + aa;
            As[d4 * 4 + 2][r] = v.z * mm + aa;
            As[d4 * 4 + 3][r] = v.w * mm + aa;
        }
        // B: 16 rows(d) x 128 cols(e)
#pragma unroll
        for (int j = 0; j < 2; j++) {
            int idx = tid + j * 256;
            int r   = idx >> 5;
            int c4  = idx & 31;
            *(float4*)(&Bs[r][c4 * 4]) =
                *(const float4*)(s1b + (size_t)(k0 + r) * DD + n0 + c4 * 4);
        }
        __syncthreads();
#pragma unroll
        for (int kk = 0; kk < 16; kk++) {
            float4 a0 = *(float4*)&As[kk][ty * 4];
            float4 a1 = *(float4*)&As[kk][ty * 4 + 64];
            float4 b0 = *(float4*)&Bs[kk][tx * 4];
            float4 b1 = *(float4*)&Bs[kk][tx * 4 + 64];
            float a[8] = {a0.x,a0.y,a0.z,a0.w, a1.x,a1.y,a1.z,a1.w};
            float bv[8] = {b0.x,b0.y,b0.z,b0.w, b1.x,b1.y,b1.z,b1.w};
#pragma unroll
            for (int i = 0; i < 8; i++)
#pragma unroll
                for (int j = 0; j < 8; j++) c[i][j] += a[i] * bv[j];
        }
        __syncthreads();
    }

    const float scale = 1.0f / 256.0f;
#pragma unroll
    for (int i = 0; i < 8; i++) {
        int mr = m0 + ty * 4 + (i & 3) + ((i >> 2) << 6);
        float* orow = Out + ((size_t)b * SS + mr) * DD + n0;
        *(float4*)(orow + tx * 4) =
            make_float4(c[i][0]*scale, c[i][1]*scale, c[i][2]*scale, c[i][3]*scale);
        *(float4*)(orow + tx * 4 + 64) =
            make_float4(c[i][4]*scale, c[i][5]*scale, c[i][6]*scale, c[i][7]*scale);
    }
}

// ---------------------------------------------------------------------------
extern "C" void kernel_launch(void* const* d_in, const int* in_sizes, int n_in,
                              void* d_out, int out_size) {
    const float* q    = (const float*)d_in[0];
    const float* k    = (const float*)d_in[1];
    const float* v    = (const float*)d_in[2];
    const void*  mask = d_in[3];
    float* out = (float*)d_out;

    k_detect<<<1, 256>>>((const unsigned int*)mask);
    k_rownorm<<<NROWS / 8, 256>>>(q, k, mask);
    k_s1<<<dim3(4, NSPLIT, BB), 256>>>(k, v);
    k_reduce<<<(BB * DD * DD) / 256, 256>>>();
    k_s2<<<dim3(2, SS / 128, BB), 256>>>(q, out);
}

// round 3
// speedup vs baseline: 1.6978x; 1.6978x over previous
#include <cuda_runtime.h>
#include <cuda_bf16.h>
#include <cstdint>

#define BB 8
#define SS 4096
#define DD 256
#define NROWS (BB*SS)
#define NEGV  (-1000000000.0f)
#define NSPLIT 4
#define KSPLIT (SS/NSPLIT)   // 1024
#define NCH1 (KSPLIT/32)     // 32
#define NCH2 (DD/32)         // 8
#define P1 272               // pitch bytes for 32-row tiles (128 bf16 cols + pad)
#define P2 80                // pitch bytes for 128-row A tiles (32 bf16 cols + pad)

// ---- scratch (no allocations allowed) ----
__device__ float g_inv_b[NROWS];
__device__ float g_mul[NROWS];
__device__ float g_s1[BB*DD*DD];
__device__ float g_s1p4[NSPLIT][BB*DD*DD];
__device__ float g_colsum[BB*DD];
__device__ int   g_mask_kind;

// ============================ helpers ============================
__device__ __forceinline__ uint32_t smem_u32(const void* p) {
    uint32_t a;
    asm("{ .reg .u64 t; cvta.to.shared.u64 t, %1; cvt.u32.u64 %0, t; }"
        : "=r"(a) : "l"(p));
    return a;
}
__device__ __forceinline__ void ldsm_x4(uint32_t* r, uint32_t a) {
    asm volatile("ldmatrix.sync.aligned.m8n8.x4.shared.b16 {%0,%1,%2,%3}, [%4];"
        : "=r"(r[0]), "=r"(r[1]), "=r"(r[2]), "=r"(r[3]) : "r"(a));
}
__device__ __forceinline__ void ldsm_x4t(uint32_t* r, uint32_t a) {
    asm volatile("ldmatrix.sync.aligned.m8n8.x4.trans.shared.b16 {%0,%1,%2,%3}, [%4];"
        : "=r"(r[0]), "=r"(r[1]), "=r"(r[2]), "=r"(r[3]) : "r"(a));
}
__device__ __forceinline__ void mma_bf16(float* c, const uint32_t* a, const uint32_t* b) {
    asm volatile(
        "mma.sync.aligned.m16n8k16.row.col.f32.bf16.bf16.f32 "
        "{%0,%1,%2,%3}, {%4,%5,%6,%7}, {%8,%9}, {%0,%1,%2,%3};"
        : "+f"(c[0]), "+f"(c[1]), "+f"(c[2]), "+f"(c[3])
        : "r"(a[0]), "r"(a[1]), "r"(a[2]), "r"(a[3]), "r"(b[0]), "r"(b[1]));
}
// split x = hi + lo (bf16 each); pack two k-consecutive elements per u32 (low = x0)
__device__ __forceinline__ void hilo(float x0, float x1, uint32_t& h, uint32_t& l) {
    __nv_bfloat162 hh = __floats2bfloat162_rn(x0, x1);
    float h0 = __bfloat162float(hh.x);
    float h1 = __bfloat162float(hh.y);
    __nv_bfloat162 ll = __floats2bfloat162_rn(x0 - h0, x1 - h1);
    h = *reinterpret_cast<uint32_t*>(&hh);
    l = *reinterpret_cast<uint32_t*>(&ll);
}

// ============================ Kernel 0: mask dtype sniff ============================
__global__ void k_detect(const unsigned int* __restrict__ m) {
    __shared__ int s_u8, s_f;
    if (threadIdx.x == 0) { s_u8 = 0; s_f = 0; }
    __syncthreads();
    for (int i = threadIdx.x; i < 8192; i += blockDim.x) {
        unsigned v = m[i];
        if (v == 0x3F800000u)      s_f  = 1;
        else if (v > 1u)           s_u8 = 1;
    }
    __syncthreads();
    if (threadIdx.x == 0) g_mask_kind = s_u8 ? 1 : (s_f ? 2 : 0);
}

// ============================ Kernel 1: row norms + mask fold ============================
__global__ void k_rownorm(const float* __restrict__ q,
                          const float* __restrict__ k,
                          const void*  __restrict__ mask) {
    int row  = blockIdx.x * 8 + (threadIdx.x >> 5);
    int lane = threadIdx.x & 31;
    const float4* q4 = (const float4*)(q + (size_t)row * DD);
    const float4* k4 = (const float4*)(k + (size_t)row * DD);
    float sa = 0.f, sb = 0.f;
#pragma unroll
    for (int j = 0; j < 2; j++) {
        float4 a = q4[lane + 32 * j];
        sa += a.x*a.x + a.y*a.y + a.z*a.z + a.w*a.w;
        float4 b = k4[lane + 32 * j];
        sb += b.x*b.x + b.y*b.y + b.z*b.z + b.w*b.w;
    }
#pragma unroll
    for (int o = 16; o; o >>= 1) {
        sa += __shfl_xor_sync(0xFFFFFFFFu, sa, o);
        sb += __shfl_xor_sync(0xFFFFFFFFu, sb, o);
    }
    if (lane == 0) {
        g_inv_b[row] = 1.0f / sb;
        int kind = g_mask_kind;
        bool ms;
        if (kind == 1)      ms = ((const unsigned char*)mask)[row] != 0;
        else if (kind == 2) ms = ((const float*)mask)[row] != 0.0f;
        else                ms = ((const int*)mask)[row] != 0;
        g_mul[row] = ms ? 0.0f : 1.0f / sa;   // mul==0 <=> masked
    }
}

// ============================ Kernel 2: GEMM1 via mma.sync bf16-split ============================
// C[d,e] = sum_s (K[s,d]*inv_b[s]) * V[s,e];  A col-major [k=s][m=d] -> ldmatrix.trans
//                                             B row-major [k=s][n=e] -> ldmatrix.trans
__global__ void __launch_bounds__(256, 1)
k_g1(const float* __restrict__ K, const float* __restrict__ V) {
    __shared__ __align__(16) char sm[4 * 32 * P1];   // Ah, Al, Bh, Bl (32 x 128 bf16 each)
    const int tid = threadIdx.x, lane = tid & 31, wid = tid >> 5;
    const int b = blockIdx.z, split = blockIdx.y;
    const int m0 = (blockIdx.x >> 1) * 128, n0 = (blockIdx.x & 1) * 128;
    const float* Kb   = K + (size_t)b * SS * DD;
    const float* Vb   = V + (size_t)b * SS * DD;
    const float* invb = g_inv_b + b * SS;

    char* Ah = sm;  char* Al = sm + 32*P1;  char* Bh = sm + 2*32*P1;  char* Bl = sm + 3*32*P1;
    const uint32_t sb = smem_u32(sm);
    const uint32_t uAh = sb, uAl = sb + 32*P1, uBh = sb + 2*32*P1, uBl = sb + 3*32*P1;

    const int sl = tid >> 3, q0 = tid & 7;           // loader: 8 threads/row, 32 rows
    float4 rk[4], rv[4]; float ib;

    const int wm = (wid >> 2) * 64, wn = (wid & 3) * 32;
    const int rowT = (lane & 7) + ((lane >> 4) << 3);   // trans-A row part (k)
    const int colT = ((lane >> 3) & 1) << 3;            // trans-A col part (m)
    const int rowB = lane & 15;                          // trans-B row part (k)
    const int colB = (lane >> 4) << 3;                   // trans-B col part (n)

    float acc[4][4][4];
#pragma unroll
    for (int i = 0; i < 4; i++)
#pragma unroll
        for (int j = 0; j < 4; j++)
#pragma unroll
            for (int t = 0; t < 4; t++) acc[i][j][t] = 0.f;

    // prefetch chunk 0
    {
        int s = split * KSPLIT + sl;
        const float* kr = Kb + (size_t)s * DD + m0;
        const float* vr = Vb + (size_t)s * DD + n0;
        ib = invb[s];
#pragma unroll
        for (int j = 0; j < 4; j++) {
            rk[j] = *(const float4*)(kr + 4 * (q0 + 8 * j));
            rv[j] = *(const float4*)(vr + 4 * (q0 + 8 * j));
        }
    }

    for (int c = 0; c < NCH1; c++) {
        __syncthreads();     // prior mma on buffer done
#pragma unroll
        for (int j = 0; j < 4; j++) {
            int q = q0 + 8 * j;
            int off = sl * P1 + 8 * q;
            uint32_t h01, l01, h23, l23;
            hilo(rk[j].x * ib, rk[j].y * ib, h01, l01);
            hilo(rk[j].z * ib, rk[j].w * ib, h23, l23);
            *(uint2*)(Ah + off) = make_uint2(h01, h23);
            *(uint2*)(Al + off) = make_uint2(l01, l23);
            hilo(rv[j].x, rv[j].y, h01, l01);
            hilo(rv[j].z, rv[j].w, h23, l23);
            *(uint2*)(Bh + off) = make_uint2(h01, h23);
            *(uint2*)(Bl + off) = make_uint2(l01, l23);
        }
        __syncthreads();
        if (c + 1 < NCH1) {  // prefetch next (overlaps mma)
            int s = split * KSPLIT + (c + 1) * 32 + sl;
            const float* kr = Kb + (size_t)s * DD + m0;
            const float* vr = Vb + (size_t)s * DD + n0;
            ib = invb[s];
#pragma unroll
            for (int j = 0; j < 4; j++) {
                rk[j] = *(const float4*)(kr + 4 * (q0 + 8 * j));
                rv[j] = *(const float4*)(vr + 4 * (q0 + 8 * j));
            }
        }
#pragma unroll
        for (int ks = 0; ks < 32; ks += 16) {
            uint32_t ah[4][4], al[4][4], bh[4][2], bl[4][2];
#pragma unroll
            for (int mf = 0; mf < 4; mf++) {
                uint32_t a = (uint32_t)((ks + rowT) * P1 + 2 * (wm + mf * 16 + colT));
                ldsm_x4t(ah[mf], uAh + a);
                ldsm_x4t(al[mf], uAl + a);
            }
#pragma unroll
            for (int nb = 0; nb < 2; nb++) {
                uint32_t a = (uint32_t)((ks + rowB) * P1 + 2 * (wn + nb * 16 + colB));
                ldsm_x4t(&bh[nb * 2][0], uBh + a);
                ldsm_x4t(&bl[nb * 2][0], uBl + a);
            }
#pragma unroll
            for (int mi = 0; mi < 4; mi++)
#pragma unroll
                for (int ni = 0; ni < 4; ni++) {
                    mma_bf16(acc[mi][ni], ah[mi], bh[ni]);
                    mma_bf16(acc[mi][ni], ah[mi], bl[ni]);
                    mma_bf16(acc[mi][ni], al[mi], bh[ni]);
                }
        }
    }

    float* out = g_s1p4[split] + (size_t)b * DD * DD;
    const int r0 = lane >> 2, cp = (lane & 3) * 2;
#pragma unroll
    for (int mi = 0; mi < 4; mi++)
#pragma unroll
        for (int ni = 0; ni < 4; ni++) {
            int m = m0 + wm + mi * 16 + r0;
            int n = n0 + wn + ni * 8 + cp;
            *(float2*)(out + (size_t)m * DD + n)       = make_float2(acc[mi][ni][0], acc[mi][ni][1]);
            *(float2*)(out + (size_t)(m + 8) * DD + n) = make_float2(acc[mi][ni][2], acc[mi][ni][3]);
        }
}

// ============================ Kernel 3: reduce split partials ============================
__global__ void k_reduce() {
    int i = blockIdx.x * 256 + threadIdx.x;
    float s = 0.f;
#pragma unroll
    for (int p = 0; p < NSPLIT; p++) s += g_s1p4[p][i];
    g_s1[i] = s;
}

// ============================ Kernel 4: column sums of s1 ============================
__global__ void k_colsum() {
    int b = blockIdx.x, e = threadIdx.x;
    const float* s1b = g_s1 + (size_t)b * DD * DD;
    float s = 0.f;
    for (int d = 0; d < DD; d++) s += s1b[d * DD + e];
    g_colsum[b * DD + e] = s;
}

// ============================ Kernel 5: GEMM2 via mma.sync bf16-split ============================
// out[s,e] = (sum_d (q[s,d]*mul[s]) * s1[d,e]) / 256 ; masked rows: NEG*colsum[e]/256
// A row-major [m=s][k=d] -> ldmatrix (non-trans); B row-major [k=d][n=e] -> ldmatrix.trans
__global__ void __launch_bounds__(256, 1)
k_g2(const float* __restrict__ Q, float* __restrict__ Out) {
    __shared__ __align__(16) char sm[2 * 128 * P2 + 2 * 32 * P1];
    const int tid = threadIdx.x, lane = tid & 31, wid = tid >> 5;
    const int b = blockIdx.z, m0 = blockIdx.y * 128, n0 = blockIdx.x * 128;
    const float* Qb  = Q + (size_t)b * SS * DD;
    const float* mul = g_mul + b * SS;
    const float* s1b = g_s1 + (size_t)b * DD * DD;

    char* Ah = sm;                 char* Al = sm + 128 * P2;
    char* Bh = sm + 2 * 128 * P2;  char* Bl = Bh + 32 * P1;
    const uint32_t sb = smem_u32(sm);
    const uint32_t uAh = sb, uAl = sb + 128 * P2;
    const uint32_t uBh = sb + 2 * 128 * P2, uBl = uBh + 32 * P1;

    // A loader: 2 threads/row, 128 rows; B loader: 8 threads/row, 32 rows
    const int ar = tid >> 1, aq0 = tid & 1;
    const int blr = tid >> 3, bq0 = tid & 7;
    float4 ra[4], rb[4]; float mm;

    const int wm = (wid >> 2) * 64, wn = (wid & 3) * 32;
    const int rowA = lane & 15;                 // non-trans A row part (m)
    const int colA = (lane >> 4) << 3;          // non-trans A col part (k)
    const int rowB = lane & 15;                 // trans B row part (k)
    const int colB = (lane >> 4) << 3;          // trans B col part (n)

    float acc[4][4][4];
#pragma unroll
    for (int i = 0; i < 4; i++)
#pragma unroll
        for (int j = 0; j < 4; j++)
#pragma unroll
            for (int t = 0; t < 4; t++) acc[i][j][t] = 0.f;

    mm = mul[m0 + ar];
    {
        const float* qr = Qb + (size_t)(m0 + ar) * DD;
#pragma unroll
        for (int j = 0; j < 4; j++) {
            ra[j] = *(const float4*)(qr + 4 * (aq0 + 2 * j));
            rb[j] = *(const float4*)(s1b + (size_t)blr * DD + n0 + 4 * (bq0 + 8 * j));
        }
    }

    for (int c = 0; c < NCH2; c++) {
        __syncthreads();
#pragma unroll
        for (int j = 0; j < 4; j++) {
            int q = aq0 + 2 * j;
            int off = ar * P2 + 8 * q;
            uint32_t h01, l01, h23, l23;
            hilo(ra[j].x * mm, ra[j].y * mm, h01, l01);
            hilo(ra[j].z * mm, ra[j].w * mm, h23, l23);
            *(uint2*)(Ah + off) = make_uint2(h01, h23);
            *(uint2*)(Al + off) = make_uint2(l01, l23);
            int qb = bq0 + 8 * j;
            int offb = blr * P1 + 8 * qb;
            hilo(rb[j].x, rb[j].y, h01, l01);
            hilo(rb[j].z, rb[j].w, h23, l23);
            *(uint2*)(Bh + offb) = make_uint2(h01, h23);
            *(uint2*)(Bl + offb) = make_uint2(l01, l23);
        }
        __syncthreads();
        if (c + 1 < NCH2) {
            int k0 = (c + 1) * 32;
            const float* qr = Qb + (size_t)(m0 + ar) * DD + k0;
#pragma unroll
            for (int j = 0; j < 4; j++) {
                ra[j] = *(const float4*)(qr + 4 * (aq0 + 2 * j));
                rb[j] = *(const float4*)(s1b + (size_t)(k0 + blr) * DD + n0 + 4 * (bq0 + 8 * j));
            }
        }
#pragma unroll
        for (int ks = 0; ks < 32; ks += 16) {
            uint32_t ah[4][4], al[4][4], bh[4][2], bl[4][2];
#pragma unroll
            for (int mf = 0; mf < 4; mf++) {
                uint32_t a = (uint32_t)((wm + mf * 16 + rowA) * P2 + 2 * (ks + colA));
                ldsm_x4(ah[mf], uAh + a);
                ldsm_x4(al[mf], uAl + a);
            }
#pragma unroll
            for (int nb = 0; nb < 2; nb++) {
                uint32_t a = (uint32_t)((ks + rowB) * P1 + 2 * (wn + nb * 16 + colB));
                ldsm_x4t(&bh[nb * 2][0], uBh + a);
                ldsm_x4t(&bl[nb * 2][0], uBl + a);
            }
#pragma unroll
            for (int mi = 0; mi < 4; mi++)
#pragma unroll
                for (int ni = 0; ni < 4; ni++) {
                    mma_bf16(acc[mi][ni], ah[mi], bh[ni]);
                    mma_bf16(acc[mi][ni], ah[mi], bl[ni]);
                    mma_bf16(acc[mi][ni], al[mi], bh[ni]);
                }
        }
    }

    const float sc = 1.0f / 256.0f;
    const float* cs = g_colsum + b * DD;
    const int r0 = lane >> 2, cp = (lane & 3) * 2;
#pragma unroll
    for (int mi = 0; mi < 4; mi++) {
        int m1 = m0 + wm + mi * 16 + r0;
        int m2 = m1 + 8;
        bool k1 = (mul[m1] == 0.0f);
        bool k2 = (mul[m2] == 0.0f);
        float* o1 = Out + ((size_t)b * SS + m1) * DD;
        float* o2 = Out + ((size_t)b * SS + m2) * DD;
#pragma unroll
        for (int ni = 0; ni < 4; ni++) {
            int n = n0 + wn + ni * 8 + cp;
            float cs0 = cs[n] * (NEGV * sc), cs1 = cs[n + 1] * (NEGV * sc);
            float v0 = k1 ? cs0 : acc[mi][ni][0] * sc;
            float v1 = k1 ? cs1 : acc[mi][ni][1] * sc;
            float v2 = k2 ? cs0 : acc[mi][ni][2] * sc;
            float v3 = k2 ? cs1 : acc[mi][ni][3] * sc;
            *(float2*)(o1 + n) = make_float2(v0, v1);
            *(float2*)(o2 + n) = make_float2(v2, v3);
        }
    }
}

// ===========================================================================
extern "C" void kernel_launch(void* const* d_in, const int* in_sizes, int n_in,
                              void* d_out, int out_size) {
    const float* q    = (const float*)d_in[0];
    const float* k    = (const float*)d_in[1];
    const float* v    = (const float*)d_in[2];
    const void*  mask = d_in[3];
    float* out = (float*)d_out;

    k_detect<<<1, 256>>>((const unsigned int*)mask);
    k_rownorm<<<NROWS / 8, 256>>>(q, k, mask);
    k_g1<<<dim3(4, NSPLIT, BB), 256>>>(k, v);
    k_reduce<<<(BB * DD * DD) / 256, 256>>>();
    k_colsum<<<BB, DD>>>();
    k_g2<<<dim3(2, SS / 128, BB), 256>>>(q, out);
}